// round 8
// baseline (speedup 1.0000x reference)
#include <cuda_runtime.h>
#include <cuda_bf16.h>
#include <cstdint>

#define NT 256

// ---------------- global scratch (no runtime allocation allowed) ----------------
static __device__ float          g_seg[(size_t)50176 * 128];      // scatter-sum
static __device__ __nv_bfloat16  g_wh[9 * 16384];                 // weight hi, fragment-major
static __device__ __nv_bfloat16  g_wl[9 * 16384];                 // weight lo, fragment-major

// ---------------- helpers ----------------
__device__ __forceinline__ void split2(float2 v, uint32_t& h, uint32_t& l) {
    __nv_bfloat162 hb = __floats2bfloat162_rn(v.x, v.y);
    float r0 = v.x - __bfloat162float(hb.x);
    float r1 = v.y - __bfloat162float(hb.y);
    __nv_bfloat162 lb = __floats2bfloat162_rn(r0, r1);
    h = *reinterpret_cast<const uint32_t*>(&hb);
    l = *reinterpret_cast<const uint32_t*>(&lb);
}
__device__ __forceinline__ void split2f(float x, float y, uint32_t& h, uint32_t& l) {
    split2(make_float2(x, y), h, l);
}
// m16n8k16 bf16 MMA, fp32 accumulate (baseline PTX, valid on sm_103)
__device__ __forceinline__ void mma4(float* c, const uint32_t* a, uint2 b) {
    asm volatile("mma.sync.aligned.m16n8k16.row.col.f32.bf16.bf16.f32 "
                 "{%0,%1,%2,%3}, {%4,%5,%6,%7}, {%8,%9}, {%0,%1,%2,%3};"
                 : "+f"(c[0]), "+f"(c[1]), "+f"(c[2]), "+f"(c[3])
                 : "r"(a[0]), "r"(a[1]), "r"(a[2]), "r"(a[3]), "r"(b.x), "r"(b.y));
}

// ---------------- prep kernels ----------------
__global__ void zero_seg_kernel(int n4) {
    int i = blockIdx.x * blockDim.x + threadIdx.x;
    if (i < n4) reinterpret_cast<float4*>(g_seg)[i] = make_float4(0.f, 0.f, 0.f, 0.f);
}
// W [Krows,128] row-major -> per-128-K-chunk fragment-major bf16 hi/lo images.
// Fragment (kstep,ntile): 32 lanes x {b0(2 bf16), b1(2 bf16)}; b0: k=2*(lane%4)+c,
// n=lane/4 (within 16x8 k-n tile); b1: k+8.
__global__ void prep_w_kernel(const float* __restrict__ W, int Krows, int baseImg) {
    int t = blockIdx.x * blockDim.x + threadIdx.x;
    if (t >= Krows * 128) return;
    int k = t >> 7, n = t & 127;
    float x = W[t];
    __nv_bfloat16 h = __float2bfloat16(x);
    __nv_bfloat16 l = __float2bfloat16(x - __bfloat162float(h));
    int chunk = k >> 7, kc = k & 127;
    int kstep = kc >> 4, kk = kc & 15;
    int reg = kk >> 3, kb = kk & 7;
    int lane = (n & 7) * 4 + (kb >> 1), cb = kb & 1;
    int frag = kstep * 16 + (n >> 3);
    size_t di = (size_t)(baseImg + chunk) * 16384 + (size_t)frag * 128 + lane * 4 + reg * 2 + cb;
    g_wh[di] = h;
    g_wl[di] = l;
}

// ---------------- SMEM map (bytes) ----------------
#define SM_BH   0        // weight chunk hi fragments (32768)
#define SM_BL   32768    // weight chunk lo fragments (32768)
#define SM_ALO  65536    // per-warp A-lo fragments  (8 warps x 4096)
#define SM_B0   98304
#define SM_B1   98816
#define SM_B2   99328
#define SM_G    99840
#define SM_BE   100352
#define SMEM_TOTAL 100864

// ---------------- fused 3-layer MLP + LN + residual (+scatter) ----------------
// One block = one 128-row tile. Warp w owns rows 16w..16w+15 (all 128 cols).
template<int NCH0, bool IS_EDGE>
__global__ __launch_bounds__(NT, 2)
void gnn_mma(const float* __restrict__ nodef,
             const float* __restrict__ edgef,
             const int*   __restrict__ senders,
             const int*   __restrict__ receivers,
             const float* __restrict__ b0, const float* __restrict__ b1,
             const float* __restrict__ b2,
             const float* __restrict__ gma, const float* __restrict__ bta,
             const float* __restrict__ resid,
             float* __restrict__ out, int M, int w0b)
{
    extern __shared__ char smem[];
    const int tid = threadIdx.x, wid = tid >> 5, lane = tid & 31, q = lane & 3;
    const int rl  = wid * 16 + (lane >> 2);       // local row (low half)
    const int r0  = blockIdx.x * 128;

    // stage biases / LN params
    for (int i = tid; i < 128; i += NT) {
        ((float*)(smem + SM_B0))[i] = b0[i];
        ((float*)(smem + SM_B1))[i] = b1[i];
        ((float*)(smem + SM_B2))[i] = b2[i];
        ((float*)(smem + SM_G ))[i] = gma[i];
        ((float*)(smem + SM_BE))[i] = bta[i];
    }

    float acc[64];
    #pragma unroll
    for (int j = 0; j < 64; ++j) acc[j] = 0.f;

    const int gel = r0 + rl, geh = gel + 8;
    const int gl = min(gel, M - 1), gh = min(geh, M - 1);

    // ================= layer 0: accumulate over NCH0 128-K chunks =================
    for (int c = 0; c < NCH0; ++c) {
        __syncthreads();   // all warps done reading previous chunk's B
        {
            const uint4* sh = (const uint4*)(g_wh + (size_t)(w0b + c) * 16384);
            const uint4* sl = (const uint4*)(g_wl + (size_t)(w0b + c) * 16384);
            uint4* dh = (uint4*)(smem + SM_BH);
            uint4* dl = (uint4*)(smem + SM_BL);
            #pragma unroll
            for (int i = tid; i < 2048; i += NT) { dh[i] = sh[i]; dl[i] = sl[i]; }
        }
        __syncthreads();

        // A source rows for this chunk
        const float* pl;
        const float* ph;
        if (IS_EDGE) {
            if (c == 0)      { pl = nodef + (size_t)senders[gl]   * 128; ph = nodef + (size_t)senders[gh]   * 128; }
            else if (c == 1) { pl = nodef + (size_t)receivers[gl] * 128; ph = nodef + (size_t)receivers[gh] * 128; }
            else             { pl = edgef + (size_t)gl * 128;            ph = edgef + (size_t)gh * 128; }
        } else {
            if (c == 0)      { pl = nodef + (size_t)gl * 128;            ph = nodef + (size_t)gh * 128; }
            else             { pl = g_seg + (size_t)gl * 128;            ph = g_seg + (size_t)gh * 128; }
        }

        #pragma unroll
        for (int s = 0; s < 8; ++s) {
            const int k0 = s * 16 + q * 2;
            uint32_t ah[4], al[4];
            split2(*(const float2*)(pl + k0),     ah[0], al[0]);
            split2(*(const float2*)(ph + k0),     ah[1], al[1]);
            split2(*(const float2*)(pl + k0 + 8), ah[2], al[2]);
            split2(*(const float2*)(ph + k0 + 8), ah[3], al[3]);
            const char* bbase = smem + (s * 16) * 256 + (lane << 3);
            #pragma unroll
            for (int t = 0; t < 16; ++t) {
                uint2 wh = *(const uint2*)(bbase + SM_BH + t * 256);
                uint2 wl = *(const uint2*)(bbase + SM_BL + t * 256);
                mma4(&acc[t * 4], ah, wh);
                mma4(&acc[t * 4], ah, wl);
                mma4(&acc[t * 4], al, wh);
            }
        }
    }

    // ================= layers 1 and 2 =================
    uint32_t Ahi[32];
    uint32_t* aloW = (uint32_t*)(smem + SM_ALO + wid * 4096);

    for (int L = 1; L <= 2; ++L) {
        // ---- transition: acc -> bias + ReLU -> split into A fragments ----
        const float* bias = (const float*)(smem + (L == 1 ? SM_B0 : SM_B1));
        #pragma unroll
        for (int s = 0; s < 8; ++s) {
            const int t0 = 2 * s, t1 = 2 * s + 1;
            float2 bz0 = *(const float2*)(bias + t0 * 8 + q * 2);
            float2 bz1 = *(const float2*)(bias + t1 * 8 + q * 2);
            float v00 = fmaxf(acc[t0 * 4 + 0] + bz0.x, 0.f);
            float v01 = fmaxf(acc[t0 * 4 + 1] + bz0.y, 0.f);
            float v02 = fmaxf(acc[t0 * 4 + 2] + bz0.x, 0.f);
            float v03 = fmaxf(acc[t0 * 4 + 3] + bz0.y, 0.f);
            float v10 = fmaxf(acc[t1 * 4 + 0] + bz1.x, 0.f);
            float v11 = fmaxf(acc[t1 * 4 + 1] + bz1.y, 0.f);
            float v12 = fmaxf(acc[t1 * 4 + 2] + bz1.x, 0.f);
            float v13 = fmaxf(acc[t1 * 4 + 3] + bz1.y, 0.f);
            uint32_t l0, l1, l2, l3;
            split2f(v00, v01, Ahi[s * 4 + 0], l0);   // a0: row lo, k in [16s,16s+8)
            split2f(v02, v03, Ahi[s * 4 + 1], l1);   // a1: row hi
            split2f(v10, v11, Ahi[s * 4 + 2], l2);   // a2: row lo, k in [16s+8,16s+16)
            split2f(v12, v13, Ahi[s * 4 + 3], l3);   // a3: row hi
            aloW[(s * 4 + 0) * 32 + lane] = l0;
            aloW[(s * 4 + 1) * 32 + lane] = l1;
            aloW[(s * 4 + 2) * 32 + lane] = l2;
            aloW[(s * 4 + 3) * 32 + lane] = l3;
        }

        // ---- load this layer's weights ----
        __syncthreads();
        {
            const int img = w0b + NCH0 - 1 + L;
            const uint4* sh = (const uint4*)(g_wh + (size_t)img * 16384);
            const uint4* sl = (const uint4*)(g_wl + (size_t)img * 16384);
            uint4* dh = (uint4*)(smem + SM_BH);
            uint4* dl = (uint4*)(smem + SM_BL);
            #pragma unroll
            for (int i = tid; i < 2048; i += NT) { dh[i] = sh[i]; dl[i] = sl[i]; }
        }
        __syncthreads();

        #pragma unroll
        for (int j = 0; j < 64; ++j) acc[j] = 0.f;

        #pragma unroll
        for (int s = 0; s < 8; ++s) {
            uint32_t al[4];
            #pragma unroll
            for (int j = 0; j < 4; ++j) al[j] = aloW[(s * 4 + j) * 32 + lane];
            const uint32_t* ah = &Ahi[s * 4];
            const char* bbase = smem + (s * 16) * 256 + (lane << 3);
            #pragma unroll
            for (int t = 0; t < 16; ++t) {
                uint2 wh = *(const uint2*)(bbase + SM_BH + t * 256);
                uint2 wl = *(const uint2*)(bbase + SM_BL + t * 256);
                mma4(&acc[t * 4], ah, wh);
                mma4(&acc[t * 4], ah, wl);
                mma4(&acc[t * 4], al, wh);
            }
        }
    }

    // ================= final: bias + LayerNorm + residual (+ scatter) =================
    {
        const float* bias = (const float*)(smem + SM_B2);
        float sl = 0.f, ssl = 0.f, sh2 = 0.f, ssh = 0.f;
        #pragma unroll
        for (int t = 0; t < 16; ++t) {
            float2 bz = *(const float2*)(bias + t * 8 + q * 2);
            float v0 = acc[t * 4 + 0] + bz.x, v1 = acc[t * 4 + 1] + bz.y;
            float v2 = acc[t * 4 + 2] + bz.x, v3 = acc[t * 4 + 3] + bz.y;
            acc[t * 4 + 0] = v0; acc[t * 4 + 1] = v1;
            acc[t * 4 + 2] = v2; acc[t * 4 + 3] = v3;
            sl += v0 + v1;  ssl = fmaf(v0, v0, fmaf(v1, v1, ssl));
            sh2 += v2 + v3; ssh = fmaf(v2, v2, fmaf(v3, v3, ssh));
        }
        // reduce across the 4 lanes sharing each row (quad butterfly)
        #pragma unroll
        for (int o = 1; o <= 2; o <<= 1) {
            sl  += __shfl_xor_sync(0xffffffffu, sl,  o);
            ssl += __shfl_xor_sync(0xffffffffu, ssl, o);
            sh2 += __shfl_xor_sync(0xffffffffu, sh2, o);
            ssh += __shfl_xor_sync(0xffffffffu, ssh, o);
        }
        const float mul = sl  * (1.f / 128.f);
        const float muh = sh2 * (1.f / 128.f);
        const float rsl = rsqrtf(ssl * (1.f / 128.f) - mul * mul + 1e-5f);
        const float rsh = rsqrtf(ssh * (1.f / 128.f) - muh * muh + 1e-5f);

        int rvl = 0, rvh = 0;
        if (IS_EDGE) { rvl = receivers[gl]; rvh = receivers[gh]; }
        const float* gw = (const float*)(smem + SM_G);
        const float* bw = (const float*)(smem + SM_BE);

        #pragma unroll
        for (int t = 0; t < 16; ++t) {
            const int col = t * 8 + q * 2;
            float2 gg = *(const float2*)(gw + col);
            float2 bb = *(const float2*)(bw + col);
            if (gel < M) {
                float ne0 = fmaf(gg.x, (acc[t * 4 + 0] - mul) * rsl, bb.x);
                float ne1 = fmaf(gg.y, (acc[t * 4 + 1] - mul) * rsl, bb.y);
                float2 rf = *(const float2*)(resid + (size_t)gel * 128 + col);
                *(float2*)(out + (size_t)gel * 128 + col) = make_float2(ne0 + rf.x, ne1 + rf.y);
                if (IS_EDGE) {
                    atomicAdd(&g_seg[(size_t)rvl * 128 + col + 0], ne0);
                    atomicAdd(&g_seg[(size_t)rvl * 128 + col + 1], ne1);
                }
            }
            if (geh < M) {
                float ne2 = fmaf(gg.x, (acc[t * 4 + 2] - muh) * rsh, bb.x);
                float ne3 = fmaf(gg.y, (acc[t * 4 + 3] - muh) * rsh, bb.y);
                float2 rf = *(const float2*)(resid + (size_t)geh * 128 + col);
                *(float2*)(out + (size_t)geh * 128 + col) = make_float2(ne2 + rf.x, ne3 + rf.y);
                if (IS_EDGE) {
                    atomicAdd(&g_seg[(size_t)rvh * 128 + col + 0], ne2);
                    atomicAdd(&g_seg[(size_t)rvh * 128 + col + 1], ne3);
                }
            }
        }
    }
}

// ---------------- launch ----------------
extern "C" void kernel_launch(void* const* d_in, const int* in_sizes, int n_in,
                              void* d_out, int out_size)
{
    const float* nodef     = (const float*)d_in[0];
    const float* edgef     = (const float*)d_in[1];
    const int*   senders   = (const int*)d_in[2];
    const int*   receivers = (const int*)d_in[3];
    const float* eW0 = (const float*)d_in[4];  const float* eb0 = (const float*)d_in[5];
    const float* eW1 = (const float*)d_in[6];  const float* eb1 = (const float*)d_in[7];
    const float* eW2 = (const float*)d_in[8];  const float* eb2 = (const float*)d_in[9];
    const float* eg  = (const float*)d_in[10]; const float* ebt = (const float*)d_in[11];
    const float* nW0 = (const float*)d_in[12]; const float* nb0 = (const float*)d_in[13];
    const float* nW1 = (const float*)d_in[14]; const float* nb1 = (const float*)d_in[15];
    const float* nW2 = (const float*)d_in[16]; const float* nb2 = (const float*)d_in[17];
    const float* ng  = (const float*)d_in[18]; const float* nbt = (const float*)d_in[19];

    const int N = in_sizes[0] / 128;
    const int E = in_sizes[2];
    float* out_node = (float*)d_out;
    float* out_edge = out_node + (size_t)N * 128;

    cudaFuncSetAttribute(gnn_mma<3, true>,
                         cudaFuncAttributeMaxDynamicSharedMemorySize, SMEM_TOTAL);
    cudaFuncSetAttribute(gnn_mma<2, false>,
                         cudaFuncAttributeMaxDynamicSharedMemorySize, SMEM_TOTAL);

    // prep: weight fragment images + zero scatter buffer
    prep_w_kernel<<<(384 * 128 + 255) / 256, 256>>>(eW0, 384, 0);
    prep_w_kernel<<<(128 * 128 + 255) / 256, 256>>>(eW1, 128, 3);
    prep_w_kernel<<<(128 * 128 + 255) / 256, 256>>>(eW2, 128, 4);
    prep_w_kernel<<<(256 * 128 + 255) / 256, 256>>>(nW0, 256, 5);
    prep_w_kernel<<<(128 * 128 + 255) / 256, 256>>>(nW1, 128, 7);
    prep_w_kernel<<<(128 * 128 + 255) / 256, 256>>>(nW2, 128, 8);
    zero_seg_kernel<<<(N * 32 + 255) / 256, 256>>>(N * 32);

    gnn_mma<3, true><<<(E + 127) / 128, NT, SMEM_TOTAL>>>(
        nodef, edgef, senders, receivers,
        eb0, eb1, eb2, eg, ebt, edgef, out_edge, E, 0);

    gnn_mma<2, false><<<(N + 127) / 128, NT, SMEM_TOTAL>>>(
        nodef, nullptr, nullptr, nullptr,
        nb0, nb1, nb2, ng, nbt, nodef, out_node, N, 5);
}

// round 9
// speedup vs baseline: 1.0185x; 1.0185x over previous
#include <cuda_runtime.h>
#include <cuda_bf16.h>
#include <cstdint>

#define NT 256

// ---------------- global scratch (no runtime allocation allowed) ----------------
static __device__ float          g_seg[(size_t)50176 * 128];   // scatter-sum
static __device__ float          g_h0s[(size_t)50176 * 128];   // nodeF @ eW0(sender)
static __device__ float          g_h0r[(size_t)50176 * 128];   // nodeF @ eW0(receiver)
static __device__ float          g_h0n[(size_t)50176 * 128];   // nodeF @ nW0(node part)
static __device__ __nv_bfloat16  g_wh[9 * 16384];              // weight hi, fragment-major
static __device__ __nv_bfloat16  g_wl[9 * 16384];              // weight lo, fragment-major

// ---------------- helpers ----------------
__device__ __forceinline__ void split2(float2 v, uint32_t& h, uint32_t& l) {
    __nv_bfloat162 hb = __floats2bfloat162_rn(v.x, v.y);
    float r0 = v.x - __bfloat162float(hb.x);
    float r1 = v.y - __bfloat162float(hb.y);
    __nv_bfloat162 lb = __floats2bfloat162_rn(r0, r1);
    h = *reinterpret_cast<const uint32_t*>(&hb);
    l = *reinterpret_cast<const uint32_t*>(&lb);
}
__device__ __forceinline__ void split2f(float x, float y, uint32_t& h, uint32_t& l) {
    split2(make_float2(x, y), h, l);
}
// m16n8k16 bf16 MMA, fp32 accumulate (baseline PTX, valid on sm_103).
// NOT volatile: lets ptxas software-pipeline independent MMAs.
__device__ __forceinline__ void mma4(float* c, const uint32_t* a, uint2 b) {
    asm("mma.sync.aligned.m16n8k16.row.col.f32.bf16.bf16.f32 "
        "{%0,%1,%2,%3}, {%4,%5,%6,%7}, {%8,%9}, {%0,%1,%2,%3};"
        : "+f"(c[0]), "+f"(c[1]), "+f"(c[2]), "+f"(c[3])
        : "r"(a[0]), "r"(a[1]), "r"(a[2]), "r"(a[3]), "r"(b.x), "r"(b.y));
}
// One K=16 step against a resident B image: 3 passes of 16 independent MMAs.
// bbase points at this s-step's hi fragments; lo fragments at +32768.
__device__ __forceinline__ void mma_pass(float* acc, const uint32_t* ah,
                                         const uint32_t* al, const char* bbase) {
    #pragma unroll
    for (int t = 0; t < 16; ++t) {
        uint2 wh = *(const uint2*)(bbase + t * 256);
        mma4(&acc[t * 4], ah, wh);
    }
    #pragma unroll
    for (int t = 0; t < 16; ++t) {
        uint2 wl = *(const uint2*)(bbase + 32768 + t * 256);
        mma4(&acc[t * 4], ah, wl);
    }
    #pragma unroll
    for (int t = 0; t < 16; ++t) {
        uint2 wh = *(const uint2*)(bbase + t * 256);
        mma4(&acc[t * 4], al, wh);
    }
}

// ---------------- prep kernels ----------------
__global__ void zero_seg_kernel(int n4) {
    int i = blockIdx.x * blockDim.x + threadIdx.x;
    if (i < n4) reinterpret_cast<float4*>(g_seg)[i] = make_float4(0.f, 0.f, 0.f, 0.f);
}
// W [Krows,128] row-major -> per-128-K-chunk fragment-major bf16 hi/lo images.
__global__ void prep_w_kernel(const float* __restrict__ W, int Krows, int baseImg) {
    int t = blockIdx.x * blockDim.x + threadIdx.x;
    if (t >= Krows * 128) return;
    int k = t >> 7, n = t & 127;
    float x = W[t];
    __nv_bfloat16 h = __float2bfloat16(x);
    __nv_bfloat16 l = __float2bfloat16(x - __bfloat162float(h));
    int chunk = k >> 7, kc = k & 127;
    int kstep = kc >> 4, kk = kc & 15;
    int reg = kk >> 3, kb = kk & 7;
    int lane = (n & 7) * 4 + (kb >> 1), cb = kb & 1;
    int frag = kstep * 16 + (n >> 3);
    size_t di = (size_t)(baseImg + chunk) * 16384 + (size_t)frag * 128 + lane * 4 + reg * 2 + cb;
    g_wh[di] = h;
    g_wl[di] = l;
}

// ---------------- SMEM maps (bytes) ----------------
// main kernels: 3 resident weight images (hi 32K + lo 32K each) + A-lo + params
#define SM_ALO  196608
#define SM_B0   229376
#define SM_B1   229888
#define SM_B2   230400
#define SM_G    230912
#define SM_BE   231424
#define SMEM_TOTAL 231936
#define SMEM_PRE   196608

// ---------------- precompute: H0s/H0r/H0n = nodeF @ {eW0s, eW0r, nW0a} ----------------
__global__ __launch_bounds__(NT, 1)
void precomp_kernel(const float* __restrict__ nodef, int Nn, int ntiles,
                    int i0, int i1, int i2)
{
    extern __shared__ char smem[];
    const int tid = threadIdx.x, wid = tid >> 5, lane = tid & 31, q = lane & 3;
    const int rl = wid * 16 + (lane >> 2);
    const int imgs[3] = {i0, i1, i2};
    for (int j = 0; j < 3; ++j) {
        const uint4* sh = (const uint4*)(g_wh + (size_t)imgs[j] * 16384);
        const uint4* sl = (const uint4*)(g_wl + (size_t)imgs[j] * 16384);
        uint4* dh = (uint4*)(smem + j * 65536);
        uint4* dl = (uint4*)(smem + j * 65536 + 32768);
        for (int i = tid; i < 2048; i += NT) { dh[i] = sh[i]; dl[i] = sl[i]; }
    }
    __syncthreads();

    float* const outs[3] = {g_h0s, g_h0r, g_h0n};
    for (int tile = blockIdx.x; tile < ntiles; tile += gridDim.x) {
        const int gel = tile * 128 + rl, geh = gel + 8;
        const int gl = min(gel, Nn - 1), gh = min(geh, Nn - 1);
        const float* pl = nodef + (size_t)gl * 128;
        const float* ph = nodef + (size_t)gh * 128;
        for (int j = 0; j < 3; ++j) {
            float acc[64];
            #pragma unroll
            for (int i = 0; i < 64; ++i) acc[i] = 0.f;
            #pragma unroll
            for (int s = 0; s < 8; ++s) {
                const int k0 = s * 16 + q * 2;
                uint32_t ahf[4], alf[4];
                split2(*(const float2*)(pl + k0),     ahf[0], alf[0]);
                split2(*(const float2*)(ph + k0),     ahf[1], alf[1]);
                split2(*(const float2*)(pl + k0 + 8), ahf[2], alf[2]);
                split2(*(const float2*)(ph + k0 + 8), ahf[3], alf[3]);
                mma_pass(acc, ahf, alf, smem + j * 65536 + (s * 16) * 256 + (lane << 3));
            }
            float* o = outs[j];
            #pragma unroll
            for (int t = 0; t < 16; ++t) {
                const int col = t * 8 + q * 2;
                if (gel < Nn)
                    *(float2*)(o + (size_t)gel * 128 + col) = make_float2(acc[t * 4 + 0], acc[t * 4 + 1]);
                if (geh < Nn)
                    *(float2*)(o + (size_t)geh * 128 + col) = make_float2(acc[t * 4 + 2], acc[t * 4 + 3]);
            }
        }
    }
}

// ---------------- fused 3-layer MLP + LN + residual (+scatter), persistent ----------------
// Warp w owns rows 16w..16w+15 of each tile entirely; weights resident; no per-tile syncs.
template<bool IS_EDGE>
__global__ __launch_bounds__(NT, 1)
void gnn2(const float* __restrict__ chunkA_in,   // edge: edgef; node: unused (g_seg)
          const int*   __restrict__ senders,
          const int*   __restrict__ receivers,
          const float* __restrict__ b0, const float* __restrict__ b1,
          const float* __restrict__ b2,
          const float* __restrict__ gma, const float* __restrict__ bta,
          const float* __restrict__ resid,
          float* __restrict__ out, int M, int ntiles, int wimg0)
{
    extern __shared__ char smem[];
    const int tid = threadIdx.x, wid = tid >> 5, lane = tid & 31, q = lane & 3;
    const int rl = tid >= 0 ? wid * 16 + (lane >> 2) : 0;

    // resident weights: 3 images
    for (int L = 0; L < 3; ++L) {
        const uint4* sh = (const uint4*)(g_wh + (size_t)(wimg0 + L) * 16384);
        const uint4* sl = (const uint4*)(g_wl + (size_t)(wimg0 + L) * 16384);
        uint4* dh = (uint4*)(smem + L * 65536);
        uint4* dl = (uint4*)(smem + L * 65536 + 32768);
        for (int i = tid; i < 2048; i += NT) { dh[i] = sh[i]; dl[i] = sl[i]; }
    }
    for (int i = tid; i < 128; i += NT) {
        ((float*)(smem + SM_B0))[i] = b0[i];
        ((float*)(smem + SM_B1))[i] = b1[i];
        ((float*)(smem + SM_B2))[i] = b2[i];
        ((float*)(smem + SM_G ))[i] = gma[i];
        ((float*)(smem + SM_BE))[i] = bta[i];
    }
    __syncthreads();

    uint32_t* aloW = (uint32_t*)(smem + SM_ALO + wid * 4096);
    const float* chunkA = IS_EDGE ? chunkA_in : g_seg;

    for (int tile = blockIdx.x; tile < ntiles; tile += gridDim.x) {
        const int gel = tile * 128 + rl, geh = gel + 8;
        const int gl = min(gel, M - 1), gh = min(geh, M - 1);

        float acc[64];

        // ---- acc init from precomputed layer-0 partials ----
        if (IS_EDGE) {
            const float* asl = g_h0s + (size_t)senders[gl]   * 128;
            const float* ash = g_h0s + (size_t)senders[gh]   * 128;
            const float* arl = g_h0r + (size_t)receivers[gl] * 128;
            const float* arh = g_h0r + (size_t)receivers[gh] * 128;
            #pragma unroll
            for (int t = 0; t < 16; ++t) {
                const int col = t * 8 + q * 2;
                float2 a = *(const float2*)(asl + col);
                float2 b = *(const float2*)(arl + col);
                float2 c = *(const float2*)(ash + col);
                float2 d = *(const float2*)(arh + col);
                acc[t * 4 + 0] = a.x + b.x; acc[t * 4 + 1] = a.y + b.y;
                acc[t * 4 + 2] = c.x + d.x; acc[t * 4 + 3] = c.y + d.y;
            }
        } else {
            const float* al_ = g_h0n + (size_t)gl * 128;
            const float* ah_ = g_h0n + (size_t)gh * 128;
            #pragma unroll
            for (int t = 0; t < 16; ++t) {
                const int col = t * 8 + q * 2;
                float2 a = *(const float2*)(al_ + col);
                float2 c = *(const float2*)(ah_ + col);
                acc[t * 4 + 0] = a.x; acc[t * 4 + 1] = a.y;
                acc[t * 4 + 2] = c.x; acc[t * 4 + 3] = c.y;
            }
        }

        // ---- layer 0: one K=128 chunk from chunkA (edgef / seg-sum) ----
        {
            const float* pl = chunkA + (size_t)gl * 128;
            const float* ph = chunkA + (size_t)gh * 128;
            #pragma unroll
            for (int s = 0; s < 8; ++s) {
                const int k0 = s * 16 + q * 2;
                uint32_t ahf[4], alf[4];
                split2(*(const float2*)(pl + k0),     ahf[0], alf[0]);
                split2(*(const float2*)(ph + k0),     ahf[1], alf[1]);
                split2(*(const float2*)(pl + k0 + 8), ahf[2], alf[2]);
                split2(*(const float2*)(ph + k0 + 8), ahf[3], alf[3]);
                mma_pass(acc, ahf, alf, smem + (s * 16) * 256 + (lane << 3));
            }
        }

        // ---- layers 1, 2 ----
        uint32_t Ahi[32];
        #pragma unroll
        for (int L = 1; L <= 2; ++L) {
            const float* bias = (const float*)(smem + (L == 1 ? SM_B0 : SM_B1));
            #pragma unroll
            for (int s = 0; s < 8; ++s) {
                const int t0 = 2 * s, t1 = 2 * s + 1;
                float2 bz0 = *(const float2*)(bias + t0 * 8 + q * 2);
                float2 bz1 = *(const float2*)(bias + t1 * 8 + q * 2);
                float v00 = fmaxf(acc[t0 * 4 + 0] + bz0.x, 0.f);
                float v01 = fmaxf(acc[t0 * 4 + 1] + bz0.y, 0.f);
                float v02 = fmaxf(acc[t0 * 4 + 2] + bz0.x, 0.f);
                float v03 = fmaxf(acc[t0 * 4 + 3] + bz0.y, 0.f);
                float v10 = fmaxf(acc[t1 * 4 + 0] + bz1.x, 0.f);
                float v11 = fmaxf(acc[t1 * 4 + 1] + bz1.y, 0.f);
                float v12 = fmaxf(acc[t1 * 4 + 2] + bz1.x, 0.f);
                float v13 = fmaxf(acc[t1 * 4 + 3] + bz1.y, 0.f);
                uint32_t l0, l1, l2, l3;
                split2f(v00, v01, Ahi[s * 4 + 0], l0);
                split2f(v02, v03, Ahi[s * 4 + 1], l1);
                split2f(v10, v11, Ahi[s * 4 + 2], l2);
                split2f(v12, v13, Ahi[s * 4 + 3], l3);
                aloW[(s * 4 + 0) * 32 + lane] = l0;
                aloW[(s * 4 + 1) * 32 + lane] = l1;
                aloW[(s * 4 + 2) * 32 + lane] = l2;
                aloW[(s * 4 + 3) * 32 + lane] = l3;
            }
            #pragma unroll
            for (int j = 0; j < 64; ++j) acc[j] = 0.f;
            #pragma unroll
            for (int s = 0; s < 8; ++s) {
                uint32_t alf[4];
                #pragma unroll
                for (int j = 0; j < 4; ++j) alf[j] = aloW[(s * 4 + j) * 32 + lane];
                mma_pass(acc, &Ahi[s * 4], alf,
                         smem + L * 65536 + (s * 16) * 256 + (lane << 3));
            }
        }

        // ---- final: bias + LayerNorm + residual (+ scatter) ----
        {
            const float* bias = (const float*)(smem + SM_B2);
            float sl = 0.f, ssl = 0.f, sh2 = 0.f, ssh = 0.f;
            #pragma unroll
            for (int t = 0; t < 16; ++t) {
                float2 bz = *(const float2*)(bias + t * 8 + q * 2);
                float v0 = acc[t * 4 + 0] + bz.x, v1 = acc[t * 4 + 1] + bz.y;
                float v2 = acc[t * 4 + 2] + bz.x, v3 = acc[t * 4 + 3] + bz.y;
                acc[t * 4 + 0] = v0; acc[t * 4 + 1] = v1;
                acc[t * 4 + 2] = v2; acc[t * 4 + 3] = v3;
                sl  += v0 + v1; ssl = fmaf(v0, v0, fmaf(v1, v1, ssl));
                sh2 += v2 + v3; ssh = fmaf(v2, v2, fmaf(v3, v3, ssh));
            }
            #pragma unroll
            for (int o = 1; o <= 2; o <<= 1) {
                sl  += __shfl_xor_sync(0xffffffffu, sl,  o);
                ssl += __shfl_xor_sync(0xffffffffu, ssl, o);
                sh2 += __shfl_xor_sync(0xffffffffu, sh2, o);
                ssh += __shfl_xor_sync(0xffffffffu, ssh, o);
            }
            const float mul = sl  * (1.f / 128.f);
            const float muh = sh2 * (1.f / 128.f);
            const float rsl = rsqrtf(ssl * (1.f / 128.f) - mul * mul + 1e-5f);
            const float rsh = rsqrtf(ssh * (1.f / 128.f) - muh * muh + 1e-5f);

            int rvl = 0, rvh = 0;
            if (IS_EDGE) { rvl = receivers[gl]; rvh = receivers[gh]; }
            const float* gw = (const float*)(smem + SM_G);
            const float* bw = (const float*)(smem + SM_BE);

            #pragma unroll
            for (int t = 0; t < 16; ++t) {
                const int col = t * 8 + q * 2;
                float2 gg = *(const float2*)(gw + col);
                float2 bb = *(const float2*)(bw + col);
                if (gel < M) {
                    float ne0 = fmaf(gg.x, (acc[t * 4 + 0] - mul) * rsl, bb.x);
                    float ne1 = fmaf(gg.y, (acc[t * 4 + 1] - mul) * rsl, bb.y);
                    float2 rf = *(const float2*)(resid + (size_t)gel * 128 + col);
                    *(float2*)(out + (size_t)gel * 128 + col) = make_float2(ne0 + rf.x, ne1 + rf.y);
                    if (IS_EDGE) {
                        atomicAdd(&g_seg[(size_t)rvl * 128 + col + 0], ne0);
                        atomicAdd(&g_seg[(size_t)rvl * 128 + col + 1], ne1);
                    }
                }
                if (geh < M) {
                    float ne2 = fmaf(gg.x, (acc[t * 4 + 2] - muh) * rsh, bb.x);
                    float ne3 = fmaf(gg.y, (acc[t * 4 + 3] - muh) * rsh, bb.y);
                    float2 rf = *(const float2*)(resid + (size_t)geh * 128 + col);
                    *(float2*)(out + (size_t)geh * 128 + col) = make_float2(ne2 + rf.x, ne3 + rf.y);
                    if (IS_EDGE) {
                        atomicAdd(&g_seg[(size_t)rvh * 128 + col + 0], ne2);
                        atomicAdd(&g_seg[(size_t)rvh * 128 + col + 1], ne3);
                    }
                }
            }
        }
    }
}

// ---------------- launch ----------------
extern "C" void kernel_launch(void* const* d_in, const int* in_sizes, int n_in,
                              void* d_out, int out_size)
{
    const float* nodef     = (const float*)d_in[0];
    const float* edgef     = (const float*)d_in[1];
    const int*   senders   = (const int*)d_in[2];
    const int*   receivers = (const int*)d_in[3];
    const float* eW0 = (const float*)d_in[4];  const float* eb0 = (const float*)d_in[5];
    const float* eW1 = (const float*)d_in[6];  const float* eb1 = (const float*)d_in[7];
    const float* eW2 = (const float*)d_in[8];  const float* eb2 = (const float*)d_in[9];
    const float* eg  = (const float*)d_in[10]; const float* ebt = (const float*)d_in[11];
    const float* nW0 = (const float*)d_in[12]; const float* nb0 = (const float*)d_in[13];
    const float* nW1 = (const float*)d_in[14]; const float* nb1 = (const float*)d_in[15];
    const float* nW2 = (const float*)d_in[16]; const float* nb2 = (const float*)d_in[17];
    const float* ng  = (const float*)d_in[18]; const float* nbt = (const float*)d_in[19];

    const int N = in_sizes[0] / 128;
    const int E = in_sizes[2];
    float* out_node = (float*)d_out;
    float* out_edge = out_node + (size_t)N * 128;

    cudaFuncSetAttribute(precomp_kernel,
                         cudaFuncAttributeMaxDynamicSharedMemorySize, SMEM_PRE);
    cudaFuncSetAttribute(gnn2<true>,
                         cudaFuncAttributeMaxDynamicSharedMemorySize, SMEM_TOTAL);
    cudaFuncSetAttribute(gnn2<false>,
                         cudaFuncAttributeMaxDynamicSharedMemorySize, SMEM_TOTAL);

    // prep: weight fragment images (imgs: 0=eW0s 1=eW0r 2=eW0e 3=eW1 4=eW2
    //                                     5=nW0a 6=nW0b 7=nW1 8=nW2) + zero scatter
    prep_w_kernel<<<(384 * 128 + 255) / 256, 256>>>(eW0, 384, 0);
    prep_w_kernel<<<(128 * 128 + 255) / 256, 256>>>(eW1, 128, 3);
    prep_w_kernel<<<(128 * 128 + 255) / 256, 256>>>(eW2, 128, 4);
    prep_w_kernel<<<(256 * 128 + 255) / 256, 256>>>(nW0, 256, 5);
    prep_w_kernel<<<(128 * 128 + 255) / 256, 256>>>(nW1, 128, 7);
    prep_w_kernel<<<(128 * 128 + 255) / 256, 256>>>(nW2, 128, 8);
    zero_seg_kernel<<<(N * 32 + 255) / 256, 256>>>(N * 32);

    const int ntile_n = (N + 127) / 128;
    const int ntile_e = (E + 127) / 128;

    // H0s / H0r / H0n precompute over nodes
    precomp_kernel<<<148, NT, SMEM_PRE>>>(nodef, N, ntile_n, 0, 1, 5);

    // edge pass (persistent)
    gnn2<true><<<148, NT, SMEM_TOTAL>>>(
        edgef, senders, receivers,
        eb0, eb1, eb2, eg, ebt, edgef, out_edge, E, ntile_e, 2);

    // node pass (persistent)
    gnn2<false><<<148, NT, SMEM_TOTAL>>>(
        nullptr, nullptr, nullptr,
        nb0, nb1, nb2, ng, nbt, nodef, out_node, N, ntile_n, 6);
}